// round 14
// baseline (speedup 1.0000x reference)
#include <cuda_runtime.h>
#include <cuda_fp16.h>
#include <stdint.h>

#define NN   50000
#define EE   800000
#define HDIM 256
#define LDIM 128
#define BN_EPS 1e-5f
#define SCAN_B 196          // ceil(NN/256)
#define KP2  40             // padded BK stride in halves (32+8) -> conflict-free ldmatrix

// ---------------- scratch (static device globals; no allocation) ----------------
__device__ float  g_dinv[NN];
__device__ int    g_cnt [NN];
__device__ int    g_ptr [NN];
__device__ int    g_pos [NN];
__device__ int    g_total;
__device__ int    g_done;
__device__ int2   g_csr [EE];                    // x=src, y=coef bits
__device__ __half g_h16[(size_t)NN * HDIM];      // GEMM out (agg in)
__device__ __half g_a16[(size_t)NN * HDIM];      // x16 / agg out (GEMM in)
__device__ float  g_stats[2 * HDIM];             // col sum / sumsq
__device__ float  g_ss   [2 * HDIM];             // scale / shift
__device__ __half g_w0t[HDIM * HDIM];            // W0^T  [n][k]
__device__ __half g_w1t[HDIM * HDIM];            // W1^T  [n][k]
__device__ __half g_wct[HDIM * HDIM];            // [Wmu|Wlv]^T [n][k]
__device__ float  g_bcat[HDIM];                  // [bmu|blv]

// ---------------- helpers ----------------
__device__ __forceinline__ void mma_f16(float* c, const uint32_t* a,
                                        uint32_t b0, uint32_t b1) {
    asm volatile(
        "mma.sync.aligned.m16n8k16.row.col.f32.f16.f16.f32 "
        "{%0,%1,%2,%3}, {%4,%5,%6,%7}, {%8,%9}, {%0,%1,%2,%3};\n"
        : "+f"(c[0]), "+f"(c[1]), "+f"(c[2]), "+f"(c[3])
        : "r"(a[0]), "r"(a[1]), "r"(a[2]), "r"(a[3]), "r"(b0), "r"(b1));
}

__device__ __forceinline__ void cp16(uint32_t dst_smem, const void* src) {
    asm volatile("cp.async.cg.shared.global [%0], [%1], 16;\n"
                 :: "r"(dst_smem), "l"(src));
}

// L1-cached variant for B (weights): reused by every co-resident block
__device__ __forceinline__ void cp16_ca(uint32_t dst_smem, const void* src) {
    asm volatile("cp.async.ca.shared.global [%0], [%1], 16;\n"
                 :: "r"(dst_smem), "l"(src));
}

__device__ __forceinline__ uint32_t bnfrag(uint32_t v, float2 sc, float2 sh) {
    float2 p = __half22float2(*(__half2*)&v);
    p.x = fmaxf(fmaf(p.x, sc.x, sh.x), 0.0f);
    p.y = fmaxf(fmaf(p.y, sc.y, sh.y), 0.0f);
    __half2 h = __floats2half2_rn(p.x, p.y);
    return *(uint32_t*)&h;
}

// ---------------- graph preprocessing ----------------
__global__ void k_cnt_zero() {
    int i = blockIdx.x * blockDim.x + threadIdx.x;
    if (i < NN) g_cnt[i] = 0;
    if (i == 0) { g_total = 0; g_done = 0; }
}

__global__ void k_cnt(const int* __restrict__ dst) {
    int e = blockIdx.x * blockDim.x + threadIdx.x;
    if (e < EE) atomicAdd(&g_cnt[dst[e]], 1);
}

// dinv + zero stats + CSR segment assignment (order-free atomic allocation)
__global__ void k_dinv() {
    int i = blockIdx.x * 256 + threadIdx.x;
    if (i < NN) {
        int c = g_cnt[i];
        g_dinv[i] = rsqrtf((float)c + 1.0f);
        int p = atomicAdd(&g_total, c);
        g_ptr[i] = p;
        g_pos[i] = p;
    }
    if (blockIdx.x == 0 && threadIdx.x < 2 * HDIM) g_stats[threadIdx.x] = 0.0f;
}

// fp16 weight transpose + head bias + x -> fp16 (NO graph dependence)
__global__ void k_wcvt(const float* __restrict__ x,
                       const float* __restrict__ W0, const float* __restrict__ W1,
                       const float* __restrict__ Wmu, const float* __restrict__ Wlv,
                       const float* __restrict__ bmu, const float* __restrict__ blv) {
    int b = blockIdx.x;
    if (b < 768) {
        int idx = b * 256 + threadIdx.x;      // 0 .. 196607
        if (idx < 65536) {
            int n = idx >> 8, k = idx & 255;
            g_w0t[idx] = __float2half(W0[k * 256 + n]);
        } else if (idx < 131072) {
            int j = idx - 65536; int n = j >> 8, k = j & 255;
            g_w1t[j] = __float2half(W1[k * 256 + n]);
        } else {
            int j = idx - 131072; int n = j >> 8, k = j & 255;
            float v = (n < 128) ? Wmu[k * 128 + n] : Wlv[k * 128 + (n - 128)];
            g_wct[j] = __float2half(v);
        }
        return;
    }
    if (b == 768) {
        int t = threadIdx.x;
        g_bcat[t] = (t < 128) ? bmu[t] : blv[t - 128];
        return;
    }
    // x conversion: 6250 blocks
    size_t j = (size_t)(b - 769) * 2048 + (size_t)threadIdx.x * 8;
    float4 v0 = *(const float4*)&x[j];
    float4 v1 = *(const float4*)&x[j + 4];
    __half2 h0 = __floats2half2_rn(v0.x, v0.y);
    __half2 h1 = __floats2half2_rn(v0.z, v0.w);
    __half2 h2 = __floats2half2_rn(v1.x, v1.y);
    __half2 h3 = __floats2half2_rn(v1.z, v1.w);
    uint4 o = make_uint4(*(uint32_t*)&h0, *(uint32_t*)&h1,
                         *(uint32_t*)&h2, *(uint32_t*)&h3);
    *(uint4*)&g_a16[j] = o;
}

__global__ void k_fill(const int* __restrict__ src, const int* __restrict__ dst) {
    int e = blockIdx.x * blockDim.x + threadIdx.x;
    if (e >= EE) return;
    int s = src[e], d = dst[e];
    int p = atomicAdd(&g_pos[d], 1);
    float c = g_dinv[s] * g_dinv[d];
    g_csr[p] = make_int2(s, __float_as_int(c));
}

// ---------------- cp.async pipelined fp16 GEMM (4-stage, tiled) ----------------
#define STG_H (128 * KP2)               // halves per (A or B) stage
#define NSTG  4
template <bool FUSE_BN, bool OUT16>
__global__ void __launch_bounds__(256, 2)
gemm_ca(const __half* __restrict__ Ah, const __half* __restrict__ Wt,
        const float* __restrict__ bias, float* __restrict__ Cf,
        __half* __restrict__ Ch, int M) {
    extern __shared__ __half sm[];

    int tid  = threadIdx.x;
    int wid  = tid >> 5, lane = tid & 31;
    int g    = lane >> 2, tg = lane & 3;
    int mb   = (wid & 3) * 32;
    int nb   = (wid >> 2) * 64;
    int rowBase = blockIdx.x * 128;
    int colBase = blockIdx.y * 128;

    uint32_t smBase = (uint32_t)__cvta_generic_to_shared(sm);

    int r_a = tid >> 2, c8_a = (tid & 3) << 3;
    int gr   = rowBase + r_a;       int gr2  = (gr   < M) ? gr   : M - 1;
    int gr_b = rowBase + r_a + 64;  int gr2b = (gr_b < M) ? gr_b : M - 1;

    auto load_stage = [&](int st, int t) {
        int k0 = t * 32;
        uint32_t aBase = smBase + (uint32_t)(st * 2 * STG_H) * 2u;
        uint32_t bBase = aBase + (uint32_t)STG_H * 2u;
        cp16(aBase + (uint32_t)(r_a * KP2 + c8_a) * 2u,
             &Ah[(size_t)gr2 * 256 + k0 + c8_a]);
        cp16(aBase + (uint32_t)((r_a + 64) * KP2 + c8_a) * 2u,
             &Ah[(size_t)gr2b * 256 + k0 + c8_a]);
        cp16_ca(bBase + (uint32_t)(r_a * KP2 + c8_a) * 2u,
                &Wt[(size_t)(colBase + r_a) * 256 + k0 + c8_a]);
        cp16_ca(bBase + (uint32_t)((r_a + 64) * KP2 + c8_a) * 2u,
                &Wt[(size_t)(colBase + r_a + 64) * 256 + k0 + c8_a]);
        asm volatile("cp.async.commit_group;\n" ::: "memory");
    };

    float acc[2][8][4] = {};

    int lm  = lane >> 3;           // ldmatrix matrix index 0..3
    int lr  = lane & 7;            // row within matrix

    load_stage(0, 0);
    load_stage(1, 1);
    load_stage(2, 2);

#pragma unroll
    for (int t = 0; t < 8; t++) {
        if (t <= 5)      asm volatile("cp.async.wait_group 2;\n" ::: "memory");
        else if (t == 6) asm volatile("cp.async.wait_group 1;\n" ::: "memory");
        else             asm volatile("cp.async.wait_group 0;\n" ::: "memory");
        __syncthreads();
        if (t + 3 < 8) load_stage((t + 3) % NSTG, t + 3);

        int st = t % NSTG;
        uint32_t aBase = smBase + (uint32_t)(st * 2 * STG_H) * 2u;
        uint32_t bBase = aBase + (uint32_t)STG_H * 2u;
        int k0 = t * 32;

#pragma unroll
        for (int ks = 0; ks < 2; ks++) {
            int kk = ks * 16;
            uint32_t a[2][4];
#pragma unroll
            for (int im = 0; im < 2; im++) {
                int row = mb + im * 16 + (lane & 15);
                int col = kk + ((lane >> 4) << 3);
                uint32_t addr = aBase + (uint32_t)(row * KP2 + col) * 2u;
                asm volatile(
                    "ldmatrix.sync.aligned.m8n8.x4.shared.b16 {%0,%1,%2,%3}, [%4];"
                    : "=r"(a[im][0]), "=r"(a[im][1]), "=r"(a[im][2]), "=r"(a[im][3])
                    : "r"(addr));
            }
            if (FUSE_BN) {
                int kb = k0 + kk + tg * 2;
                float2 sA = *(const float2*)&g_ss[kb];
                float2 hA = *(const float2*)&g_ss[256 + kb];
                float2 sB = *(const float2*)&g_ss[kb + 8];
                float2 hB = *(const float2*)&g_ss[256 + kb + 8];
#pragma unroll
                for (int im = 0; im < 2; im++) {
                    a[im][0] = bnfrag(a[im][0], sA, hA);
                    a[im][1] = bnfrag(a[im][1], sA, hA);
                    a[im][2] = bnfrag(a[im][2], sB, hB);
                    a[im][3] = bnfrag(a[im][3], sB, hB);
                }
            }
            uint32_t bf[8][2];
#pragma unroll
            for (int ntp = 0; ntp < 4; ntp++) {
                int row_n = nb + ntp * 16 + ((lm >> 1) << 3) + lr;
                int col   = kk + ((lm & 1) << 3);
                uint32_t addr = bBase + (uint32_t)(row_n * KP2 + col) * 2u;
                asm volatile(
                    "ldmatrix.sync.aligned.m8n8.x4.shared.b16 {%0,%1,%2,%3}, [%4];"
                    : "=r"(bf[ntp * 2][0]),     "=r"(bf[ntp * 2][1]),
                      "=r"(bf[ntp * 2 + 1][0]), "=r"(bf[ntp * 2 + 1][1])
                    : "r"(addr));
            }
#pragma unroll
            for (int nt = 0; nt < 8; nt++) {
                mma_f16(acc[0][nt], a[0], bf[nt][0], bf[nt][1]);
                mma_f16(acc[1][nt], a[1], bf[nt][0], bf[nt][1]);
            }
        }
    }

    // ---- epilogue ----
#pragma unroll
    for (int im = 0; im < 2; im++) {
#pragma unroll
        for (int nt = 0; nt < 8; nt++) {
            int row0 = rowBase + mb + im * 16 + g;
            int col  = colBase + nb + nt * 8 + tg * 2;
            float bx = 0.f, by = 0.f;
            if (bias) { bx = bias[col]; by = bias[col + 1]; }
#pragma unroll
            for (int h = 0; h < 2; h++) {
                int row = row0 + h * 8;
                if (row < M) {
                    float ox = acc[im][nt][h * 2 + 0] + bx;
                    float oy = acc[im][nt][h * 2 + 1] + by;
                    if (OUT16) {
                        *(__half2*)&Ch[(size_t)row * 256 + col] =
                            __floats2half2_rn(ox, oy);
                    } else {
                        if (col < 128)
                            *(float2*)&Cf[(size_t)row * 128 + col] =
                                make_float2(ox, oy);
                        else
                            *(float2*)&Cf[(size_t)NN * 128 + (size_t)row * 128 + (col - 128)] =
                                make_float2(ox, oy);
                    }
                }
            }
        }
    }
}

// ---------------- CSR aggregation, MLP=4, + fused BN stats + last-block BN ----
__device__ __forceinline__ void fma8(float* acc, uint4 r, float c) {
    __half2* hp = (__half2*)&r;
#pragma unroll
    for (int q = 0; q < 4; q++) {
        float2 p = __half22float2(hp[q]);
        acc[q * 2]     += c * p.x;
        acc[q * 2 + 1] += c * p.y;
    }
}

__global__ void k_agg_csr(const __half* __restrict__ h, __half* __restrict__ out,
                          const float* __restrict__ bias,
                          const float* __restrict__ gamma,
                          const float* __restrict__ beta) {
    __shared__ float s_sum[8][256];
    __shared__ float s_sq [8][256];
    __shared__ bool  s_last;

    int grp  = threadIdx.x >> 5;     // 0..7
    int lane = threadIdx.x & 31;
    int node = blockIdx.x * 8 + grp;
    int f = lane * 8;

    float acc[8] = {};
    if (node < NN) {
        float di = g_dinv[node];
        float cs = di * di;
#pragma unroll
        for (int q = 0; q < 8; q++) acc[q] = bias[f + q];
        fma8(acc, *(const uint4*)&h[(size_t)node * 256 + f], cs);

        int beg = g_ptr[node];
        int end = beg + g_cnt[node];
        int2 rec = make_int2(0, 0);
        if (lane < 4 && beg + lane < end) rec = g_csr[beg + lane];

        for (int j = beg; j < end; j += 4) {
            int2 cur = rec;
            int jn = j + 4;
            int2 nx = make_int2(0, 0);
            if (lane < 4 && jn + lane < end) nx = g_csr[jn + lane];
            rec = nx;
            int take = end - j;      // warp-uniform

            int   s0 = __shfl_sync(0xffffffffu, cur.x, 0);
            float c0 = __int_as_float(__shfl_sync(0xffffffffu, cur.y, 0));
            int   s1 = __shfl_sync(0xffffffffu, cur.x, 1);
            float c1 = __int_as_float(__shfl_sync(0xffffffffu, cur.y, 1));
            int   s2 = __shfl_sync(0xffffffffu, cur.x, 2);
            float c2 = __int_as_float(__shfl_sync(0xffffffffu, cur.y, 2));
            int   s3 = __shfl_sync(0xffffffffu, cur.x, 3);
            float c3 = __int_as_float(__shfl_sync(0xffffffffu, cur.y, 3));

            uint4 r0 = *(const uint4*)&h[(size_t)s0 * 256 + f];
            if (take > 1) {
                uint4 r1 = *(const uint4*)&h[(size_t)s1 * 256 + f];
                if (take > 2) {
                    uint4 r2 = *(const uint4*)&h[(size_t)s2 * 256 + f];
                    if (take > 3) {
                        uint4 r3 = *(const uint4*)&h[(size_t)s3 * 256 + f];
                        fma8(acc, r3, c3);
                    }
                    fma8(acc, r2, c2);
                }
                fma8(acc, r1, c1);
            }
            fma8(acc, r0, c0);
        }

        __half2 o0 = __floats2half2_rn(acc[0], acc[1]);
        __half2 o1 = __floats2half2_rn(acc[2], acc[3]);
        __half2 o2 = __floats2half2_rn(acc[4], acc[5]);
        __half2 o3 = __floats2half2_rn(acc[6], acc[7]);
        uint4 ov = make_uint4(*(uint32_t*)&o0, *(uint32_t*)&o1,
                              *(uint32_t*)&o2, *(uint32_t*)&o3);
        *(uint4*)&out[(size_t)node * 256 + f] = ov;
    }

#pragma unroll
    for (int q = 0; q < 8; q++) {
        s_sum[grp][f + q] = acc[q];
        s_sq [grp][f + q] = acc[q] * acc[q];
    }
    __syncthreads();

    int t = threadIdx.x;   // feature
    float s = 0.f, q = 0.f;
#pragma unroll
    for (int gi = 0; gi < 8; gi++) { s += s_sum[gi][t]; q += s_sq[gi][t]; }
    atomicAdd(&g_stats[t], s);
    atomicAdd(&g_stats[HDIM + t], q);

    // last-arriving block computes BN scale/shift and resets stats
    __threadfence();
    if (t == 0) {
        int v = atomicAdd(&g_done, 1);
        s_last = (v == (int)gridDim.x - 1);
    }
    __syncthreads();
    if (s_last) {
        float inv_n = 1.0f / (float)NN;
        float m  = g_stats[t] * inv_n;
        float vv = g_stats[HDIM + t] * inv_n - m * m;
        float sc = gamma[t] * rsqrtf(vv + BN_EPS);
        g_ss[t]        = sc;
        g_ss[HDIM + t] = beta[t] - m * sc;
        g_stats[t] = 0.0f;
        g_stats[HDIM + t] = 0.0f;
        if (t == 0) g_done = 0;
    }
}

// ---------------- launch ----------------
extern "C" void kernel_launch(void* const* d_in, const int* in_sizes, int n_in,
                              void* d_out, int out_size) {
    const float* x   = (const float*)d_in[0];
    const int*   ei  = (const int*)  d_in[1];   // [2, E]: src then dst
    const float* W0  = (const float*)d_in[2];
    const float* b0  = (const float*)d_in[3];
    const float* g0  = (const float*)d_in[4];
    const float* be0 = (const float*)d_in[5];
    const float* W1  = (const float*)d_in[6];
    const float* b1  = (const float*)d_in[7];
    const float* g1  = (const float*)d_in[8];
    const float* be1 = (const float*)d_in[9];
    const float* Wmu = (const float*)d_in[10];
    const float* bmu = (const float*)d_in[11];
    const float* Wlv = (const float*)d_in[12];
    const float* blv = (const float*)d_in[13];
    float* out = (float*)d_out;

    const int* src = ei;
    const int* dst = ei + EE;

    __half *h16 = nullptr, *a16 = nullptr, *w0t = nullptr, *w1t = nullptr, *wct = nullptr;
    float  *bcat = nullptr;
    cudaGetSymbolAddress((void**)&h16,  g_h16);
    cudaGetSymbolAddress((void**)&a16,  g_a16);
    cudaGetSymbolAddress((void**)&w0t,  g_w0t);
    cudaGetSymbolAddress((void**)&w1t,  g_w1t);
    cudaGetSymbolAddress((void**)&wct,  g_wct);
    cudaGetSymbolAddress((void**)&bcat, g_bcat);

    // side streams + events (created once, outside any capture)
    static cudaStream_t s1 = nullptr, s2 = nullptr;
    static cudaEvent_t  evF = nullptr, evGemm = nullptr, evDinv = nullptr, evCsr = nullptr;
    if (!s1) {
        cudaStreamCreateWithFlags(&s1, cudaStreamNonBlocking);
        cudaStreamCreateWithFlags(&s2, cudaStreamNonBlocking);
        cudaEventCreateWithFlags(&evF,    cudaEventDisableTiming);
        cudaEventCreateWithFlags(&evGemm, cudaEventDisableTiming);
        cudaEventCreateWithFlags(&evDinv, cudaEventDisableTiming);
        cudaEventCreateWithFlags(&evCsr,  cudaEventDisableTiming);
    }

    const int NB_N  = SCAN_B;
    const int NB_E  = (EE + 255) / 256;
    const int NB_AG = (NN + 7) / 8;             // 6250
    const int NB_W  = 769 + 6250;               // weights + bias + x-convert
    const dim3 G_GEMM((NN + 127) / 128, 2);     // 391 x 2

    const int SMEM = NSTG * 2 * STG_H * 2;      // 81920 bytes
    cudaFuncSetAttribute(gemm_ca<false, true>,
                         cudaFuncAttributeMaxDynamicSharedMemorySize, SMEM);
    cudaFuncSetAttribute(gemm_ca<true, true>,
                         cudaFuncAttributeMaxDynamicSharedMemorySize, SMEM);
    cudaFuncSetAttribute(gemm_ca<true, false>,
                         cudaFuncAttributeMaxDynamicSharedMemorySize, SMEM);

    // fork point
    cudaEventRecord(evF, 0);

    // chain A (s1): weight/x conversion -> layer-0 GEMM (independent of graph)
    cudaStreamWaitEvent(s1, evF, 0);
    k_wcvt<<<NB_W, 256, 0, s1>>>(x, W0, W1, Wmu, Wlv, bmu, blv);
    gemm_ca<false, true><<<G_GEMM, 256, SMEM, s1>>>(a16, w0t, nullptr, nullptr, h16, NN);
    cudaEventRecord(evGemm, s1);

    // chain B (default): degree counts -> dinv+ptr
    k_cnt_zero<<<NB_N, 256>>>();
    k_cnt     <<<NB_E, 256>>>(dst);
    k_dinv    <<<NB_N, 256>>>();
    cudaEventRecord(evDinv, 0);

    // chain C (s2): CSR fill (needs dinv+ptr)
    cudaStreamWaitEvent(s2, evDinv, 0);
    k_fill<<<NB_E, 256, 0, s2>>>(src, dst);
    cudaEventRecord(evCsr, s2);

    // join everything on default stream
    cudaStreamWaitEvent(0, evGemm, 0);
    cudaStreamWaitEvent(0, evCsr, 0);

    // layer 0: agg (+BN coeffs in last block)
    k_agg_csr<<<NB_AG, 256>>>(h16, a16, b0, g0, be0);

    // layer 1
    gemm_ca<true, true><<<G_GEMM, 256, SMEM>>>(a16, w1t, nullptr, nullptr, h16, NN);
    k_agg_csr<<<NB_AG, 256>>>(h16, a16, b1, g1, be1);

    // heads: combined mu|logvar GEMM with split epilogue
    gemm_ca<true, false><<<G_GEMM, 256, SMEM>>>(a16, wct, bcat, out, nullptr, NN);
}

// round 15
// speedup vs baseline: 1.0462x; 1.0462x over previous
#include <cuda_runtime.h>
#include <cuda_fp16.h>
#include <stdint.h>

#define NN   50000
#define EE   800000
#define HDIM 256
#define LDIM 128
#define BN_EPS 1e-5f
#define SCAN_B 196          // ceil(NN/256)
#define KP2  40             // padded BK stride in halves (32+8) -> conflict-free ldmatrix

// ---------------- scratch (static device globals; no allocation) ----------------
__device__ float  g_dinv[NN];
__device__ int    g_cnt [NN];
__device__ int    g_ptr [NN];
__device__ int    g_pos [NN];
__device__ int    g_total;
__device__ int2   g_csr [EE];                    // x=src, y=coef bits
__device__ __half g_h16[(size_t)NN * HDIM];      // GEMM out (agg in)
__device__ __half g_a16[(size_t)NN * HDIM];      // x16 / agg out (GEMM in)
__device__ float  g_stats[2 * HDIM];             // col sum / sumsq
__device__ float  g_ss   [2 * HDIM];             // scale / shift
__device__ __half g_w0t[HDIM * HDIM];            // W0^T  [n][k]
__device__ __half g_w1t[HDIM * HDIM];            // W1^T  [n][k]
__device__ __half g_wct[HDIM * HDIM];            // [Wmu|Wlv]^T [n][k]
__device__ float  g_bcat[HDIM];                  // [bmu|blv]

// ---------------- helpers ----------------
__device__ __forceinline__ void mma_f16(float* c, const uint32_t* a,
                                        uint32_t b0, uint32_t b1) {
    asm volatile(
        "mma.sync.aligned.m16n8k16.row.col.f32.f16.f16.f32 "
        "{%0,%1,%2,%3}, {%4,%5,%6,%7}, {%8,%9}, {%0,%1,%2,%3};\n"
        : "+f"(c[0]), "+f"(c[1]), "+f"(c[2]), "+f"(c[3])
        : "r"(a[0]), "r"(a[1]), "r"(a[2]), "r"(a[3]), "r"(b0), "r"(b1));
}

// L1-cached cp.async: used for both A (sibling-block reuse via flattened grid)
// and B (co-resident-block reuse)
__device__ __forceinline__ void cp16_ca(uint32_t dst_smem, const void* src) {
    asm volatile("cp.async.ca.shared.global [%0], [%1], 16;\n"
                 :: "r"(dst_smem), "l"(src));
}

__device__ __forceinline__ uint32_t bnfrag(uint32_t v, float2 sc, float2 sh) {
    float2 p = __half22float2(*(__half2*)&v);
    p.x = fmaxf(fmaf(p.x, sc.x, sh.x), 0.0f);
    p.y = fmaxf(fmaf(p.y, sc.y, sh.y), 0.0f);
    __half2 h = __floats2half2_rn(p.x, p.y);
    return *(uint32_t*)&h;
}

// ---------------- graph preprocessing ----------------
__global__ void k_cnt_zero() {
    int i = blockIdx.x * blockDim.x + threadIdx.x;
    if (i < NN) g_cnt[i] = 0;
    if (i == 0) g_total = 0;
}

__global__ void k_cnt(const int* __restrict__ dst) {
    int e = blockIdx.x * blockDim.x + threadIdx.x;
    if (e < EE) atomicAdd(&g_cnt[dst[e]], 1);
}

// dinv + zero stats (depends on g_cnt)
__global__ void k_dinv() {
    int i = blockIdx.x * 256 + threadIdx.x;
    if (i < NN) g_dinv[i] = rsqrtf((float)g_cnt[i] + 1.0f);
    if (blockIdx.x == 0 && threadIdx.x < 2 * HDIM) g_stats[threadIdx.x] = 0.0f;
}

// fp16 weight transpose + head bias + x -> fp16 (NO graph dependence)
__global__ void k_wcvt(const float* __restrict__ x,
                       const float* __restrict__ W0, const float* __restrict__ W1,
                       const float* __restrict__ Wmu, const float* __restrict__ Wlv,
                       const float* __restrict__ bmu, const float* __restrict__ blv) {
    int b = blockIdx.x;
    if (b < 768) {
        int idx = b * 256 + threadIdx.x;      // 0 .. 196607
        if (idx < 65536) {
            int n = idx >> 8, k = idx & 255;
            g_w0t[idx] = __float2half(W0[k * 256 + n]);
        } else if (idx < 131072) {
            int j = idx - 65536; int n = j >> 8, k = j & 255;
            g_w1t[j] = __float2half(W1[k * 256 + n]);
        } else {
            int j = idx - 131072; int n = j >> 8, k = j & 255;
            float v = (n < 128) ? Wmu[k * 128 + n] : Wlv[k * 128 + (n - 128)];
            g_wct[j] = __float2half(v);
        }
        return;
    }
    if (b == 768) {
        int t = threadIdx.x;
        g_bcat[t] = (t < 128) ? bmu[t] : blv[t - 128];
        return;
    }
    // x conversion: 6250 blocks
    size_t j = (size_t)(b - 769) * 2048 + (size_t)threadIdx.x * 8;
    float4 v0 = *(const float4*)&x[j];
    float4 v1 = *(const float4*)&x[j + 4];
    __half2 h0 = __floats2half2_rn(v0.x, v0.y);
    __half2 h1 = __floats2half2_rn(v0.z, v0.w);
    __half2 h2 = __floats2half2_rn(v1.x, v1.y);
    __half2 h3 = __floats2half2_rn(v1.z, v1.w);
    uint4 o = make_uint4(*(uint32_t*)&h0, *(uint32_t*)&h1,
                         *(uint32_t*)&h2, *(uint32_t*)&h3);
    *(uint4*)&g_a16[j] = o;
}

// CSR segment assignment: order-free atomic allocation
__global__ void k_ptra() {
    int i = blockIdx.x * blockDim.x + threadIdx.x;
    if (i < NN) {
        int c = g_cnt[i];
        int p = atomicAdd(&g_total, c);
        g_ptr[i] = p;
        g_pos[i] = p;
    }
}

__global__ void k_fill(const int* __restrict__ src, const int* __restrict__ dst) {
    int e = blockIdx.x * blockDim.x + threadIdx.x;
    if (e >= EE) return;
    int s = src[e], d = dst[e];
    int p = atomicAdd(&g_pos[d], 1);
    float c = g_dinv[s] * g_dinv[d];
    g_csr[p] = make_int2(s, __float_as_int(c));
}

// ---------------- cp.async pipelined fp16 GEMM (4-stage, flattened grid) ------
// Grid: 1-D, 2 blocks per M-tile; bid>>1 = M-tile, bid&1 = col-half. Sibling
// blocks (2x, 2x+1) share the A tile -> .ca gives L1 reuse on A and B.
#define STG_H (128 * KP2)               // halves per (A or B) stage
#define NSTG  4
template <bool FUSE_BN, bool OUT16>
__global__ void __launch_bounds__(256, 2)
gemm_ca(const __half* __restrict__ Ah, const __half* __restrict__ Wt,
        const float* __restrict__ bias, float* __restrict__ Cf,
        __half* __restrict__ Ch, int M) {
    extern __shared__ __half sm[];

    int tid  = threadIdx.x;
    int wid  = tid >> 5, lane = tid & 31;
    int g    = lane >> 2, tg = lane & 3;
    int mb   = (wid & 3) * 32;
    int nb   = (wid >> 2) * 64;
    int bid  = blockIdx.x;
    int rowBase = (bid >> 1) * 128;
    int colBase = (bid & 1) * 128;

    uint32_t smBase = (uint32_t)__cvta_generic_to_shared(sm);

    int r_a = tid >> 2, c8_a = (tid & 3) << 3;
    int gr   = rowBase + r_a;       int gr2  = (gr   < M) ? gr   : M - 1;
    int gr_b = rowBase + r_a + 64;  int gr2b = (gr_b < M) ? gr_b : M - 1;

    auto load_stage = [&](int st, int t) {
        int k0 = t * 32;
        uint32_t aBase = smBase + (uint32_t)(st * 2 * STG_H) * 2u;
        uint32_t bBase = aBase + (uint32_t)STG_H * 2u;
        cp16_ca(aBase + (uint32_t)(r_a * KP2 + c8_a) * 2u,
                &Ah[(size_t)gr2 * 256 + k0 + c8_a]);
        cp16_ca(aBase + (uint32_t)((r_a + 64) * KP2 + c8_a) * 2u,
                &Ah[(size_t)gr2b * 256 + k0 + c8_a]);
        cp16_ca(bBase + (uint32_t)(r_a * KP2 + c8_a) * 2u,
                &Wt[(size_t)(colBase + r_a) * 256 + k0 + c8_a]);
        cp16_ca(bBase + (uint32_t)((r_a + 64) * KP2 + c8_a) * 2u,
                &Wt[(size_t)(colBase + r_a + 64) * 256 + k0 + c8_a]);
        asm volatile("cp.async.commit_group;\n" ::: "memory");
    };

    float acc[2][8][4] = {};

    int lm  = lane >> 3;           // ldmatrix matrix index 0..3
    int lr  = lane & 7;            // row within matrix

    load_stage(0, 0);
    load_stage(1, 1);
    load_stage(2, 2);

#pragma unroll
    for (int t = 0; t < 8; t++) {
        if (t <= 5)      asm volatile("cp.async.wait_group 2;\n" ::: "memory");
        else if (t == 6) asm volatile("cp.async.wait_group 1;\n" ::: "memory");
        else             asm volatile("cp.async.wait_group 0;\n" ::: "memory");
        __syncthreads();
        if (t + 3 < 8) load_stage((t + 3) % NSTG, t + 3);

        int st = t % NSTG;
        uint32_t aBase = smBase + (uint32_t)(st * 2 * STG_H) * 2u;
        uint32_t bBase = aBase + (uint32_t)STG_H * 2u;
        int k0 = t * 32;

#pragma unroll
        for (int ks = 0; ks < 2; ks++) {
            int kk = ks * 16;
            uint32_t a[2][4];
#pragma unroll
            for (int im = 0; im < 2; im++) {
                int row = mb + im * 16 + (lane & 15);
                int col = kk + ((lane >> 4) << 3);
                uint32_t addr = aBase + (uint32_t)(row * KP2 + col) * 2u;
                asm volatile(
                    "ldmatrix.sync.aligned.m8n8.x4.shared.b16 {%0,%1,%2,%3}, [%4];"
                    : "=r"(a[im][0]), "=r"(a[im][1]), "=r"(a[im][2]), "=r"(a[im][3])
                    : "r"(addr));
            }
            if (FUSE_BN) {
                int kb = k0 + kk + tg * 2;
                float2 sA = *(const float2*)&g_ss[kb];
                float2 hA = *(const float2*)&g_ss[256 + kb];
                float2 sB = *(const float2*)&g_ss[kb + 8];
                float2 hB = *(const float2*)&g_ss[256 + kb + 8];
#pragma unroll
                for (int im = 0; im < 2; im++) {
                    a[im][0] = bnfrag(a[im][0], sA, hA);
                    a[im][1] = bnfrag(a[im][1], sA, hA);
                    a[im][2] = bnfrag(a[im][2], sB, hB);
                    a[im][3] = bnfrag(a[im][3], sB, hB);
                }
            }
            uint32_t bf[8][2];
#pragma unroll
            for (int ntp = 0; ntp < 4; ntp++) {
                int row_n = nb + ntp * 16 + ((lm >> 1) << 3) + lr;
                int col   = kk + ((lm & 1) << 3);
                uint32_t addr = bBase + (uint32_t)(row_n * KP2 + col) * 2u;
                asm volatile(
                    "ldmatrix.sync.aligned.m8n8.x4.shared.b16 {%0,%1,%2,%3}, [%4];"
                    : "=r"(bf[ntp * 2][0]),     "=r"(bf[ntp * 2][1]),
                      "=r"(bf[ntp * 2 + 1][0]), "=r"(bf[ntp * 2 + 1][1])
                    : "r"(addr));
            }
#pragma unroll
            for (int nt = 0; nt < 8; nt++) {
                mma_f16(acc[0][nt], a[0], bf[nt][0], bf[nt][1]);
                mma_f16(acc[1][nt], a[1], bf[nt][0], bf[nt][1]);
            }
        }
    }

    // ---- epilogue ----
#pragma unroll
    for (int im = 0; im < 2; im++) {
#pragma unroll
        for (int nt = 0; nt < 8; nt++) {
            int row0 = rowBase + mb + im * 16 + g;
            int col  = colBase + nb + nt * 8 + tg * 2;
            float bx = 0.f, by = 0.f;
            if (bias) { bx = bias[col]; by = bias[col + 1]; }
#pragma unroll
            for (int h = 0; h < 2; h++) {
                int row = row0 + h * 8;
                if (row < M) {
                    float ox = acc[im][nt][h * 2 + 0] + bx;
                    float oy = acc[im][nt][h * 2 + 1] + by;
                    if (OUT16) {
                        *(__half2*)&Ch[(size_t)row * 256 + col] =
                            __floats2half2_rn(ox, oy);
                    } else {
                        if (col < 128)
                            *(float2*)&Cf[(size_t)row * 128 + col] =
                                make_float2(ox, oy);
                        else
                            *(float2*)&Cf[(size_t)NN * 128 + (size_t)row * 128 + (col - 128)] =
                                make_float2(ox, oy);
                    }
                }
            }
        }
    }
}

// ---------------- CSR aggregation, MLP=4 (proven), + fused BN stats ----------
__device__ __forceinline__ void fma8(float* acc, uint4 r, float c) {
    __half2* hp = (__half2*)&r;
#pragma unroll
    for (int q = 0; q < 4; q++) {
        float2 p = __half22float2(hp[q]);
        acc[q * 2]     += c * p.x;
        acc[q * 2 + 1] += c * p.y;
    }
}

__global__ void k_agg_csr(const __half* __restrict__ h, __half* __restrict__ out,
                          const float* __restrict__ bias) {
    __shared__ float s_sum[8][256];
    __shared__ float s_sq [8][256];

    int grp  = threadIdx.x >> 5;     // 0..7
    int lane = threadIdx.x & 31;
    int node = blockIdx.x * 8 + grp;
    int f = lane * 8;

    float acc[8] = {};
    if (node < NN) {
        float di = g_dinv[node];
        float cs = di * di;
#pragma unroll
        for (int q = 0; q < 8; q++) acc[q] = bias[f + q];
        fma8(acc, *(const uint4*)&h[(size_t)node * 256 + f], cs);

        int beg = g_ptr[node];
        int end = beg + g_cnt[node];
        int2 rec = make_int2(0, 0);
        if (lane < 4 && beg + lane < end) rec = g_csr[beg + lane];

        for (int j = beg; j < end; j += 4) {
            int2 cur = rec;
            int jn = j + 4;
            int2 nx = make_int2(0, 0);
            if (lane < 4 && jn + lane < end) nx = g_csr[jn + lane];
            rec = nx;
            int take = end - j;      // warp-uniform

            int   s0 = __shfl_sync(0xffffffffu, cur.x, 0);
            float c0 = __int_as_float(__shfl_sync(0xffffffffu, cur.y, 0));
            int   s1 = __shfl_sync(0xffffffffu, cur.x, 1);
            float c1 = __int_as_float(__shfl_sync(0xffffffffu, cur.y, 1));
            int   s2 = __shfl_sync(0xffffffffu, cur.x, 2);
            float c2 = __int_as_float(__shfl_sync(0xffffffffu, cur.y, 2));
            int   s3 = __shfl_sync(0xffffffffu, cur.x, 3);
            float c3 = __int_as_float(__shfl_sync(0xffffffffu, cur.y, 3));

            uint4 r0 = *(const uint4*)&h[(size_t)s0 * 256 + f];
            if (take > 1) {
                uint4 r1 = *(const uint4*)&h[(size_t)s1 * 256 + f];
                if (take > 2) {
                    uint4 r2 = *(const uint4*)&h[(size_t)s2 * 256 + f];
                    if (take > 3) {
                        uint4 r3 = *(const uint4*)&h[(size_t)s3 * 256 + f];
                        fma8(acc, r3, c3);
                    }
                    fma8(acc, r2, c2);
                }
                fma8(acc, r1, c1);
            }
            fma8(acc, r0, c0);
        }

        __half2 o0 = __floats2half2_rn(acc[0], acc[1]);
        __half2 o1 = __floats2half2_rn(acc[2], acc[3]);
        __half2 o2 = __floats2half2_rn(acc[4], acc[5]);
        __half2 o3 = __floats2half2_rn(acc[6], acc[7]);
        uint4 ov = make_uint4(*(uint32_t*)&o0, *(uint32_t*)&o1,
                              *(uint32_t*)&o2, *(uint32_t*)&o3);
        *(uint4*)&out[(size_t)node * 256 + f] = ov;
    }

#pragma unroll
    for (int q = 0; q < 8; q++) {
        s_sum[grp][f + q] = acc[q];
        s_sq [grp][f + q] = acc[q] * acc[q];
    }
    __syncthreads();

    int t = threadIdx.x;   // feature
    float s = 0.f, q = 0.f;
#pragma unroll
    for (int gi = 0; gi < 8; gi++) { s += s_sum[gi][t]; q += s_sq[gi][t]; }
    atomicAdd(&g_stats[t], s);
    atomicAdd(&g_stats[HDIM + t], q);
}

__global__ void k_bn_final(const float* __restrict__ gamma, const float* __restrict__ beta) {
    int f = threadIdx.x;
    float inv_n = 1.0f / (float)NN;
    float m  = g_stats[f] * inv_n;
    float v  = g_stats[HDIM + f] * inv_n - m * m;
    float sc = gamma[f] * rsqrtf(v + BN_EPS);
    g_ss[f]        = sc;
    g_ss[HDIM + f] = beta[f] - m * sc;
    g_stats[f] = 0.0f;
    g_stats[HDIM + f] = 0.0f;
}

// ---------------- launch ----------------
extern "C" void kernel_launch(void* const* d_in, const int* in_sizes, int n_in,
                              void* d_out, int out_size) {
    const float* x   = (const float*)d_in[0];
    const int*   ei  = (const int*)  d_in[1];   // [2, E]: src then dst
    const float* W0  = (const float*)d_in[2];
    const float* b0  = (const float*)d_in[3];
    const float* g0  = (const float*)d_in[4];
    const float* be0 = (const float*)d_in[5];
    const float* W1  = (const float*)d_in[6];
    const float* b1  = (const float*)d_in[7];
    const float* g1  = (const float*)d_in[8];
    const float* be1 = (const float*)d_in[9];
    const float* Wmu = (const float*)d_in[10];
    const float* bmu = (const float*)d_in[11];
    const float* Wlv = (const float*)d_in[12];
    const float* blv = (const float*)d_in[13];
    float* out = (float*)d_out;

    const int* src = ei;
    const int* dst = ei + EE;

    __half *h16 = nullptr, *a16 = nullptr, *w0t = nullptr, *w1t = nullptr, *wct = nullptr;
    float  *bcat = nullptr;
    cudaGetSymbolAddress((void**)&h16,  g_h16);
    cudaGetSymbolAddress((void**)&a16,  g_a16);
    cudaGetSymbolAddress((void**)&w0t,  g_w0t);
    cudaGetSymbolAddress((void**)&w1t,  g_w1t);
    cudaGetSymbolAddress((void**)&wct,  g_wct);
    cudaGetSymbolAddress((void**)&bcat, g_bcat);

    // side streams + events (created once, outside any capture)
    static cudaStream_t s1 = nullptr, s2 = nullptr;
    static cudaEvent_t  evF = nullptr, evGemm = nullptr, evDinv = nullptr, evCsr = nullptr;
    if (!s1) {
        cudaStreamCreateWithFlags(&s1, cudaStreamNonBlocking);
        cudaStreamCreateWithFlags(&s2, cudaStreamNonBlocking);
        cudaEventCreateWithFlags(&evF,    cudaEventDisableTiming);
        cudaEventCreateWithFlags(&evGemm, cudaEventDisableTiming);
        cudaEventCreateWithFlags(&evDinv, cudaEventDisableTiming);
        cudaEventCreateWithFlags(&evCsr,  cudaEventDisableTiming);
    }

    const int NB_N  = SCAN_B;
    const int NB_E  = (EE + 255) / 256;
    const int NB_AG = (NN + 7) / 8;             // 6250
    const int NB_W  = 769 + 6250;               // weights + bias + x-convert
    const int G_GEMM = ((NN + 127) / 128) * 2;  // 782, flattened

    const int SMEM = NSTG * 2 * STG_H * 2;      // 81920 bytes
    cudaFuncSetAttribute(gemm_ca<false, true>,
                         cudaFuncAttributeMaxDynamicSharedMemorySize, SMEM);
    cudaFuncSetAttribute(gemm_ca<true, true>,
                         cudaFuncAttributeMaxDynamicSharedMemorySize, SMEM);
    cudaFuncSetAttribute(gemm_ca<true, false>,
                         cudaFuncAttributeMaxDynamicSharedMemorySize, SMEM);

    // fork point
    cudaEventRecord(evF, 0);

    // chain A (s1): weight/x conversion -> layer-0 GEMM (independent of graph)
    cudaStreamWaitEvent(s1, evF, 0);
    k_wcvt<<<NB_W, 256, 0, s1>>>(x, W0, W1, Wmu, Wlv, bmu, blv);
    gemm_ca<false, true><<<G_GEMM, 256, SMEM, s1>>>(a16, w0t, nullptr, nullptr, h16, NN);
    cudaEventRecord(evGemm, s1);

    // chain B (default): degree counts -> dinv
    k_cnt_zero<<<NB_N, 256>>>();
    k_cnt     <<<NB_E, 256>>>(dst);
    k_dinv    <<<NB_N, 256>>>();
    cudaEventRecord(evDinv, 0);

    // chain C (s2): CSR build (needs dinv)
    cudaStreamWaitEvent(s2, evDinv, 0);
    k_ptra<<<NB_N, 256, 0, s2>>>();
    k_fill<<<NB_E, 256, 0, s2>>>(src, dst);
    cudaEventRecord(evCsr, s2);

    // join everything on default stream
    cudaStreamWaitEvent(0, evGemm, 0);
    cudaStreamWaitEvent(0, evCsr, 0);

    // layer 0 aggregation + BN coeffs
    k_agg_csr <<<NB_AG, 256>>>(h16, a16, b0);
    k_bn_final<<<1, 256>>>(g0, be0);

    // layer 1
    gemm_ca<true, true><<<G_GEMM, 256, SMEM>>>(a16, w1t, nullptr, nullptr, h16, NN);
    k_agg_csr <<<NB_AG, 256>>>(h16, a16, b1);
    k_bn_final<<<1, 256>>>(g1, be1);

    // heads: combined mu|logvar GEMM with split epilogue
    gemm_ca<true, false><<<G_GEMM, 256, SMEM>>>(a16, wct, bcat, out, nullptr, NN);
}

// round 16
// speedup vs baseline: 1.0545x; 1.0079x over previous
#include <cuda_runtime.h>
#include <cuda_fp16.h>
#include <stdint.h>

#define NN   50000
#define EE   800000
#define HDIM 256
#define LDIM 128
#define BN_EPS 1e-5f
#define SCAN_B 196          // ceil(NN/256)
#define KP2  40             // padded BK stride in halves (32+8) -> conflict-free ldmatrix

// ---------------- scratch (static device globals; no allocation) ----------------
__device__ float  g_dinv[NN];
__device__ int    g_cnt [NN];
__device__ int    g_ptr [NN];
__device__ int    g_pos [NN];
__device__ int    g_total;
__device__ int2   g_csr [EE];                    // x=src, y=coef bits
__device__ __half g_h16[(size_t)NN * HDIM];      // GEMM out (agg in)
__device__ __half g_a16[(size_t)NN * HDIM];      // x16 / agg out (GEMM in)
__device__ float  g_stats[2 * HDIM];             // col sum / sumsq
__device__ float  g_ss   [2 * HDIM];             // scale / shift
__device__ __half g_w0t[HDIM * HDIM];            // W0^T  [n][k]
__device__ __half g_w1t[HDIM * HDIM];            // W1^T  [n][k]
__device__ __half g_wct[HDIM * HDIM];            // [Wmu|Wlv]^T [n][k]
__device__ float  g_bcat[HDIM];                  // [bmu|blv]

// ---------------- helpers ----------------
__device__ __forceinline__ void mma_f16(float* c, const uint32_t* a,
                                        uint32_t b0, uint32_t b1) {
    asm volatile(
        "mma.sync.aligned.m16n8k16.row.col.f32.f16.f16.f32 "
        "{%0,%1,%2,%3}, {%4,%5,%6,%7}, {%8,%9}, {%0,%1,%2,%3};\n"
        : "+f"(c[0]), "+f"(c[1]), "+f"(c[2]), "+f"(c[3])
        : "r"(a[0]), "r"(a[1]), "r"(a[2]), "r"(a[3]), "r"(b0), "r"(b1));
}

__device__ __forceinline__ void cp16(uint32_t dst_smem, const void* src) {
    asm volatile("cp.async.cg.shared.global [%0], [%1], 16;\n"
                 :: "r"(dst_smem), "l"(src));
}

// L1-cached variant for B (weights): reused by every co-resident block
__device__ __forceinline__ void cp16_ca(uint32_t dst_smem, const void* src) {
    asm volatile("cp.async.ca.shared.global [%0], [%1], 16;\n"
                 :: "r"(dst_smem), "l"(src));
}

__device__ __forceinline__ uint32_t bnfrag(uint32_t v, float2 sc, float2 sh) {
    float2 p = __half22float2(*(__half2*)&v);
    p.x = fmaxf(fmaf(p.x, sc.x, sh.x), 0.0f);
    p.y = fmaxf(fmaf(p.y, sc.y, sh.y), 0.0f);
    __half2 h = __floats2half2_rn(p.x, p.y);
    return *(uint32_t*)&h;
}

// ---------------- graph preprocessing ----------------
__global__ void k_cnt_zero() {
    int i = blockIdx.x * blockDim.x + threadIdx.x;
    if (i < NN) g_cnt[i] = 0;
    if (i == 0) g_total = 0;
}

__global__ void k_cnt(const int* __restrict__ dst) {
    int e = blockIdx.x * blockDim.x + threadIdx.x;
    if (e < EE) atomicAdd(&g_cnt[dst[e]], 1);
}

// dinv + zero stats + CSR segment assignment (order-free atomic allocation)
__global__ void k_dinv() {
    int i = blockIdx.x * 256 + threadIdx.x;
    if (i < NN) {
        int c = g_cnt[i];
        g_dinv[i] = rsqrtf((float)c + 1.0f);
        int p = atomicAdd(&g_total, c);
        g_ptr[i] = p;
        g_pos[i] = p;
    }
    if (blockIdx.x == 0 && threadIdx.x < 2 * HDIM) g_stats[threadIdx.x] = 0.0f;
}

// fp16 weight transpose + head bias + x -> fp16 (NO graph dependence)
__global__ void k_wcvt(const float* __restrict__ x,
                       const float* __restrict__ W0, const float* __restrict__ W1,
                       const float* __restrict__ Wmu, const float* __restrict__ Wlv,
                       const float* __restrict__ bmu, const float* __restrict__ blv) {
    int b = blockIdx.x;
    if (b < 768) {
        int idx = b * 256 + threadIdx.x;      // 0 .. 196607
        if (idx < 65536) {
            int n = idx >> 8, k = idx & 255;
            g_w0t[idx] = __float2half(W0[k * 256 + n]);
        } else if (idx < 131072) {
            int j = idx - 65536; int n = j >> 8, k = j & 255;
            g_w1t[j] = __float2half(W1[k * 256 + n]);
        } else {
            int j = idx - 131072; int n = j >> 8, k = j & 255;
            float v = (n < 128) ? Wmu[k * 128 + n] : Wlv[k * 128 + (n - 128)];
            g_wct[j] = __float2half(v);
        }
        return;
    }
    if (b == 768) {
        int t = threadIdx.x;
        g_bcat[t] = (t < 128) ? bmu[t] : blv[t - 128];
        return;
    }
    // x conversion: 6250 blocks
    size_t j = (size_t)(b - 769) * 2048 + (size_t)threadIdx.x * 8;
    float4 v0 = *(const float4*)&x[j];
    float4 v1 = *(const float4*)&x[j + 4];
    __half2 h0 = __floats2half2_rn(v0.x, v0.y);
    __half2 h1 = __floats2half2_rn(v0.z, v0.w);
    __half2 h2 = __floats2half2_rn(v1.x, v1.y);
    __half2 h3 = __floats2half2_rn(v1.z, v1.w);
    uint4 o = make_uint4(*(uint32_t*)&h0, *(uint32_t*)&h1,
                         *(uint32_t*)&h2, *(uint32_t*)&h3);
    *(uint4*)&g_a16[j] = o;
}

__global__ void k_fill(const int* __restrict__ src, const int* __restrict__ dst) {
    int e = blockIdx.x * blockDim.x + threadIdx.x;
    if (e >= EE) return;
    int s = src[e], d = dst[e];
    int p = atomicAdd(&g_pos[d], 1);
    float c = g_dinv[s] * g_dinv[d];
    g_csr[p] = make_int2(s, __float_as_int(c));
}

// ---------------- cp.async pipelined fp16 GEMM (4-stage, 2-D grid) ------------
#define STG_H (128 * KP2)               // halves per (A or B) stage
#define NSTG  4
template <bool FUSE_BN, bool OUT16>
__global__ void __launch_bounds__(256, 2)
gemm_ca(const __half* __restrict__ Ah, const __half* __restrict__ Wt,
        const float* __restrict__ bias, float* __restrict__ Cf,
        __half* __restrict__ Ch, int M) {
    extern __shared__ __half sm[];

    int tid  = threadIdx.x;
    int wid  = tid >> 5, lane = tid & 31;
    int g    = lane >> 2, tg = lane & 3;
    int mb   = (wid & 3) * 32;
    int nb   = (wid >> 2) * 64;
    int rowBase = blockIdx.x * 128;
    int colBase = blockIdx.y * 128;

    uint32_t smBase = (uint32_t)__cvta_generic_to_shared(sm);

    int r_a = tid >> 2, c8_a = (tid & 3) << 3;
    int gr   = rowBase + r_a;       int gr2  = (gr   < M) ? gr   : M - 1;
    int gr_b = rowBase + r_a + 64;  int gr2b = (gr_b < M) ? gr_b : M - 1;

    auto load_stage = [&](int st, int t) {
        int k0 = t * 32;
        uint32_t aBase = smBase + (uint32_t)(st * 2 * STG_H) * 2u;
        uint32_t bBase = aBase + (uint32_t)STG_H * 2u;
        cp16(aBase + (uint32_t)(r_a * KP2 + c8_a) * 2u,
             &Ah[(size_t)gr2 * 256 + k0 + c8_a]);
        cp16(aBase + (uint32_t)((r_a + 64) * KP2 + c8_a) * 2u,
             &Ah[(size_t)gr2b * 256 + k0 + c8_a]);
        cp16_ca(bBase + (uint32_t)(r_a * KP2 + c8_a) * 2u,
                &Wt[(size_t)(colBase + r_a) * 256 + k0 + c8_a]);
        cp16_ca(bBase + (uint32_t)((r_a + 64) * KP2 + c8_a) * 2u,
                &Wt[(size_t)(colBase + r_a + 64) * 256 + k0 + c8_a]);
        asm volatile("cp.async.commit_group;\n" ::: "memory");
    };

    float acc[2][8][4] = {};

    int lm  = lane >> 3;           // ldmatrix matrix index 0..3
    int lr  = lane & 7;            // row within matrix

    load_stage(0, 0);
    load_stage(1, 1);
    load_stage(2, 2);

#pragma unroll
    for (int t = 0; t < 8; t++) {
        if (t <= 5)      asm volatile("cp.async.wait_group 2;\n" ::: "memory");
        else if (t == 6) asm volatile("cp.async.wait_group 1;\n" ::: "memory");
        else             asm volatile("cp.async.wait_group 0;\n" ::: "memory");
        __syncthreads();
        if (t + 3 < 8) load_stage((t + 3) % NSTG, t + 3);

        int st = t % NSTG;
        uint32_t aBase = smBase + (uint32_t)(st * 2 * STG_H) * 2u;
        uint32_t bBase = aBase + (uint32_t)STG_H * 2u;
        int k0 = t * 32;

#pragma unroll
        for (int ks = 0; ks < 2; ks++) {
            int kk = ks * 16;
            uint32_t a[2][4];
#pragma unroll
            for (int im = 0; im < 2; im++) {
                int row = mb + im * 16 + (lane & 15);
                int col = kk + ((lane >> 4) << 3);
                uint32_t addr = aBase + (uint32_t)(row * KP2 + col) * 2u;
                asm volatile(
                    "ldmatrix.sync.aligned.m8n8.x4.shared.b16 {%0,%1,%2,%3}, [%4];"
                    : "=r"(a[im][0]), "=r"(a[im][1]), "=r"(a[im][2]), "=r"(a[im][3])
                    : "r"(addr));
            }
            if (FUSE_BN) {
                int kb = k0 + kk + tg * 2;
                float2 sA = *(const float2*)&g_ss[kb];
                float2 hA = *(const float2*)&g_ss[256 + kb];
                float2 sB = *(const float2*)&g_ss[kb + 8];
                float2 hB = *(const float2*)&g_ss[256 + kb + 8];
#pragma unroll
                for (int im = 0; im < 2; im++) {
                    a[im][0] = bnfrag(a[im][0], sA, hA);
                    a[im][1] = bnfrag(a[im][1], sA, hA);
                    a[im][2] = bnfrag(a[im][2], sB, hB);
                    a[im][3] = bnfrag(a[im][3], sB, hB);
                }
            }
            uint32_t bf[8][2];
#pragma unroll
            for (int ntp = 0; ntp < 4; ntp++) {
                int row_n = nb + ntp * 16 + ((lm >> 1) << 3) + lr;
                int col   = kk + ((lm & 1) << 3);
                uint32_t addr = bBase + (uint32_t)(row_n * KP2 + col) * 2u;
                asm volatile(
                    "ldmatrix.sync.aligned.m8n8.x4.shared.b16 {%0,%1,%2,%3}, [%4];"
                    : "=r"(bf[ntp * 2][0]),     "=r"(bf[ntp * 2][1]),
                      "=r"(bf[ntp * 2 + 1][0]), "=r"(bf[ntp * 2 + 1][1])
                    : "r"(addr));
            }
#pragma unroll
            for (int nt = 0; nt < 8; nt++) {
                mma_f16(acc[0][nt], a[0], bf[nt][0], bf[nt][1]);
                mma_f16(acc[1][nt], a[1], bf[nt][0], bf[nt][1]);
            }
        }
    }

    // ---- epilogue ----
#pragma unroll
    for (int im = 0; im < 2; im++) {
#pragma unroll
        for (int nt = 0; nt < 8; nt++) {
            int row0 = rowBase + mb + im * 16 + g;
            int col  = colBase + nb + nt * 8 + tg * 2;
            float bx = 0.f, by = 0.f;
            if (bias) { bx = bias[col]; by = bias[col + 1]; }
#pragma unroll
            for (int h = 0; h < 2; h++) {
                int row = row0 + h * 8;
                if (row < M) {
                    float ox = acc[im][nt][h * 2 + 0] + bx;
                    float oy = acc[im][nt][h * 2 + 1] + by;
                    if (OUT16) {
                        *(__half2*)&Ch[(size_t)row * 256 + col] =
                            __floats2half2_rn(ox, oy);
                    } else {
                        if (col < 128)
                            *(float2*)&Cf[(size_t)row * 128 + col] =
                                make_float2(ox, oy);
                        else
                            *(float2*)&Cf[(size_t)NN * 128 + (size_t)row * 128 + (col - 128)] =
                                make_float2(ox, oy);
                    }
                }
            }
        }
    }
}

// ---------------- CSR aggregation, MLP=4 (proven), + fused BN stats ----------
__device__ __forceinline__ void fma8(float* acc, uint4 r, float c) {
    __half2* hp = (__half2*)&r;
#pragma unroll
    for (int q = 0; q < 4; q++) {
        float2 p = __half22float2(hp[q]);
        acc[q * 2]     += c * p.x;
        acc[q * 2 + 1] += c * p.y;
    }
}

__global__ void k_agg_csr(const __half* __restrict__ h, __half* __restrict__ out,
                          const float* __restrict__ bias) {
    __shared__ float s_sum[8][256];
    __shared__ float s_sq [8][256];

    int grp  = threadIdx.x >> 5;     // 0..7
    int lane = threadIdx.x & 31;
    int node = blockIdx.x * 8 + grp;
    int f = lane * 8;

    float acc[8] = {};
    if (node < NN) {
        float di = g_dinv[node];
        float cs = di * di;
#pragma unroll
        for (int q = 0; q < 8; q++) acc[q] = bias[f + q];
        fma8(acc, *(const uint4*)&h[(size_t)node * 256 + f], cs);

        int beg = g_ptr[node];
        int end = beg + g_cnt[node];
        int2 rec = make_int2(0, 0);
        if (lane < 4 && beg + lane < end) rec = g_csr[beg + lane];

        for (int j = beg; j < end; j += 4) {
            int2 cur = rec;
            int jn = j + 4;
            int2 nx = make_int2(0, 0);
            if (lane < 4 && jn + lane < end) nx = g_csr[jn + lane];
            rec = nx;
            int take = end - j;      // warp-uniform

            int   s0 = __shfl_sync(0xffffffffu, cur.x, 0);
            float c0 = __int_as_float(__shfl_sync(0xffffffffu, cur.y, 0));
            int   s1 = __shfl_sync(0xffffffffu, cur.x, 1);
            float c1 = __int_as_float(__shfl_sync(0xffffffffu, cur.y, 1));
            int   s2 = __shfl_sync(0xffffffffu, cur.x, 2);
            float c2 = __int_as_float(__shfl_sync(0xffffffffu, cur.y, 2));
            int   s3 = __shfl_sync(0xffffffffu, cur.x, 3);
            float c3 = __int_as_float(__shfl_sync(0xffffffffu, cur.y, 3));

            uint4 r0 = *(const uint4*)&h[(size_t)s0 * 256 + f];
            if (take > 1) {
                uint4 r1 = *(const uint4*)&h[(size_t)s1 * 256 + f];
                if (take > 2) {
                    uint4 r2 = *(const uint4*)&h[(size_t)s2 * 256 + f];
                    if (take > 3) {
                        uint4 r3 = *(const uint4*)&h[(size_t)s3 * 256 + f];
                        fma8(acc, r3, c3);
                    }
                    fma8(acc, r2, c2);
                }
                fma8(acc, r1, c1);
            }
            fma8(acc, r0, c0);
        }

        __half2 o0 = __floats2half2_rn(acc[0], acc[1]);
        __half2 o1 = __floats2half2_rn(acc[2], acc[3]);
        __half2 o2 = __floats2half2_rn(acc[4], acc[5]);
        __half2 o3 = __floats2half2_rn(acc[6], acc[7]);
        uint4 ov = make_uint4(*(uint32_t*)&o0, *(uint32_t*)&o1,
                              *(uint32_t*)&o2, *(uint32_t*)&o3);
        *(uint4*)&out[(size_t)node * 256 + f] = ov;
    }

#pragma unroll
    for (int q = 0; q < 8; q++) {
        s_sum[grp][f + q] = acc[q];
        s_sq [grp][f + q] = acc[q] * acc[q];
    }
    __syncthreads();

    int t = threadIdx.x;   // feature
    float s = 0.f, q = 0.f;
#pragma unroll
    for (int gi = 0; gi < 8; gi++) { s += s_sum[gi][t]; q += s_sq[gi][t]; }
    atomicAdd(&g_stats[t], s);
    atomicAdd(&g_stats[HDIM + t], q);
}

__global__ void k_bn_final(const float* __restrict__ gamma, const float* __restrict__ beta) {
    int f = threadIdx.x;
    float inv_n = 1.0f / (float)NN;
    float m  = g_stats[f] * inv_n;
    float v  = g_stats[HDIM + f] * inv_n - m * m;
    float sc = gamma[f] * rsqrtf(v + BN_EPS);
    g_ss[f]        = sc;
    g_ss[HDIM + f] = beta[f] - m * sc;
    g_stats[f] = 0.0f;
    g_stats[HDIM + f] = 0.0f;
}

// ---------------- launch ----------------
extern "C" void kernel_launch(void* const* d_in, const int* in_sizes, int n_in,
                              void* d_out, int out_size) {
    const float* x   = (const float*)d_in[0];
    const int*   ei  = (const int*)  d_in[1];   // [2, E]: src then dst
    const float* W0  = (const float*)d_in[2];
    const float* b0  = (const float*)d_in[3];
    const float* g0  = (const float*)d_in[4];
    const float* be0 = (const float*)d_in[5];
    const float* W1  = (const float*)d_in[6];
    const float* b1  = (const float*)d_in[7];
    const float* g1  = (const float*)d_in[8];
    const float* be1 = (const float*)d_in[9];
    const float* Wmu = (const float*)d_in[10];
    const float* bmu = (const float*)d_in[11];
    const float* Wlv = (const float*)d_in[12];
    const float* blv = (const float*)d_in[13];
    float* out = (float*)d_out;

    const int* src = ei;
    const int* dst = ei + EE;

    __half *h16 = nullptr, *a16 = nullptr, *w0t = nullptr, *w1t = nullptr, *wct = nullptr;
    float  *bcat = nullptr;
    cudaGetSymbolAddress((void**)&h16,  g_h16);
    cudaGetSymbolAddress((void**)&a16,  g_a16);
    cudaGetSymbolAddress((void**)&w0t,  g_w0t);
    cudaGetSymbolAddress((void**)&w1t,  g_w1t);
    cudaGetSymbolAddress((void**)&wct,  g_wct);
    cudaGetSymbolAddress((void**)&bcat, g_bcat);

    // side streams + events (created once, outside any capture)
    static cudaStream_t s1 = nullptr, s2 = nullptr;
    static cudaEvent_t  evF = nullptr, evGemm = nullptr, evDinv = nullptr, evCsr = nullptr;
    if (!s1) {
        cudaStreamCreateWithFlags(&s1, cudaStreamNonBlocking);
        cudaStreamCreateWithFlags(&s2, cudaStreamNonBlocking);
        cudaEventCreateWithFlags(&evF,    cudaEventDisableTiming);
        cudaEventCreateWithFlags(&evGemm, cudaEventDisableTiming);
        cudaEventCreateWithFlags(&evDinv, cudaEventDisableTiming);
        cudaEventCreateWithFlags(&evCsr,  cudaEventDisableTiming);
    }

    const int NB_N  = SCAN_B;
    const int NB_E  = (EE + 255) / 256;
    const int NB_AG = (NN + 7) / 8;             // 6250
    const int NB_W  = 769 + 6250;               // weights + bias + x-convert
    const dim3 G_GEMM((NN + 127) / 128, 2);     // 391 x 2

    const int SMEM = NSTG * 2 * STG_H * 2;      // 81920 bytes
    cudaFuncSetAttribute(gemm_ca<false, true>,
                         cudaFuncAttributeMaxDynamicSharedMemorySize, SMEM);
    cudaFuncSetAttribute(gemm_ca<true, true>,
                         cudaFuncAttributeMaxDynamicSharedMemorySize, SMEM);
    cudaFuncSetAttribute(gemm_ca<true, false>,
                         cudaFuncAttributeMaxDynamicSharedMemorySize, SMEM);

    // fork point
    cudaEventRecord(evF, 0);

    // chain A (s1): weight/x conversion -> layer-0 GEMM (independent of graph)
    cudaStreamWaitEvent(s1, evF, 0);
    k_wcvt<<<NB_W, 256, 0, s1>>>(x, W0, W1, Wmu, Wlv, bmu, blv);
    gemm_ca<false, true><<<G_GEMM, 256, SMEM, s1>>>(a16, w0t, nullptr, nullptr, h16, NN);
    cudaEventRecord(evGemm, s1);

    // chain B (default): degree counts -> dinv+ptr (fused)
    k_cnt_zero<<<NB_N, 256>>>();
    k_cnt     <<<NB_E, 256>>>(dst);
    k_dinv    <<<NB_N, 256>>>();
    cudaEventRecord(evDinv, 0);

    // chain C (s2): CSR fill (needs dinv+ptr)
    cudaStreamWaitEvent(s2, evDinv, 0);
    k_fill<<<NB_E, 256, 0, s2>>>(src, dst);
    cudaEventRecord(evCsr, s2);

    // join everything on default stream
    cudaStreamWaitEvent(0, evGemm, 0);
    cudaStreamWaitEvent(0, evCsr, 0);

    // layer 0 aggregation + BN coeffs
    k_agg_csr <<<NB_AG, 256>>>(h16, a16, b0);
    k_bn_final<<<1, 256>>>(g0, be0);

    // layer 1
    gemm_ca<true, true><<<G_GEMM, 256, SMEM>>>(a16, w1t, nullptr, nullptr, h16, NN);
    k_agg_csr <<<NB_AG, 256>>>(h16, a16, b1);
    k_bn_final<<<1, 256>>>(g1, be1);

    // heads: combined mu|logvar GEMM with split epilogue
    gemm_ca<true, false><<<G_GEMM, 256, SMEM>>>(a16, wct, bcat, out, nullptr, NN);
}

// round 17
// speedup vs baseline: 1.0631x; 1.0081x over previous
#include <cuda_runtime.h>
#include <cuda_fp16.h>
#include <stdint.h>

#define NN   50000
#define EE   800000
#define HDIM 256
#define LDIM 128
#define BN_EPS 1e-5f
#define SCAN_B 196          // ceil(NN/256)
#define KP2  40             // padded BK stride in halves (32+8) -> conflict-free ldmatrix

// ---------------- scratch (static device globals; no allocation) ----------------
__device__ float  g_dinv[NN];
__device__ int    g_cnt [NN];
__device__ int    g_ptr [NN];
__device__ int    g_pos [NN];
__device__ int    g_total;
__device__ int2   g_csr [EE];                    // x=src, y=coef bits
__device__ __half g_h16[(size_t)NN * HDIM];      // GEMM out (agg in)
__device__ __half g_a16[(size_t)NN * HDIM];      // x16 / agg out (GEMM in)
__device__ float  g_stats0[2 * HDIM];            // layer-0 col sum / sumsq
__device__ float  g_stats1[2 * HDIM];            // layer-1 col sum / sumsq
__device__ __half g_w0t[HDIM * HDIM];            // W0^T  [n][k]
__device__ __half g_w1t[HDIM * HDIM];            // W1^T  [n][k]
__device__ __half g_wct[HDIM * HDIM];            // [Wmu|Wlv]^T [n][k]
__device__ float  g_bcat[HDIM];                  // [bmu|blv]

// ---------------- helpers ----------------
__device__ __forceinline__ void mma_f16(float* c, const uint32_t* a,
                                        uint32_t b0, uint32_t b1) {
    asm volatile(
        "mma.sync.aligned.m16n8k16.row.col.f32.f16.f16.f32 "
        "{%0,%1,%2,%3}, {%4,%5,%6,%7}, {%8,%9}, {%0,%1,%2,%3};\n"
        : "+f"(c[0]), "+f"(c[1]), "+f"(c[2]), "+f"(c[3])
        : "r"(a[0]), "r"(a[1]), "r"(a[2]), "r"(a[3]), "r"(b0), "r"(b1));
}

__device__ __forceinline__ void cp16(uint32_t dst_smem, const void* src) {
    asm volatile("cp.async.cg.shared.global [%0], [%1], 16;\n"
                 :: "r"(dst_smem), "l"(src));
}

// L1-cached variant for B (weights): reused by every co-resident block
__device__ __forceinline__ void cp16_ca(uint32_t dst_smem, const void* src) {
    asm volatile("cp.async.ca.shared.global [%0], [%1], 16;\n"
                 :: "r"(dst_smem), "l"(src));
}

__device__ __forceinline__ uint32_t bnfrag(uint32_t v, float2 sc, float2 sh) {
    float2 p = __half22float2(*(__half2*)&v);
    p.x = fmaxf(fmaf(p.x, sc.x, sh.x), 0.0f);
    p.y = fmaxf(fmaf(p.y, sc.y, sh.y), 0.0f);
    __half2 h = __floats2half2_rn(p.x, p.y);
    return *(uint32_t*)&h;
}

// ---------------- graph preprocessing ----------------
__global__ void k_cnt_zero() {
    int i = blockIdx.x * blockDim.x + threadIdx.x;
    if (i < NN) g_cnt[i] = 0;
    if (i == 0) g_total = 0;
}

__global__ void k_cnt(const int* __restrict__ dst) {
    int e = blockIdx.x * blockDim.x + threadIdx.x;
    if (e < EE) atomicAdd(&g_cnt[dst[e]], 1);
}

// dinv + zero both stats buffers + CSR segment assignment
__global__ void k_dinv() {
    int i = blockIdx.x * 256 + threadIdx.x;
    if (i < NN) {
        int c = g_cnt[i];
        g_dinv[i] = rsqrtf((float)c + 1.0f);
        int p = atomicAdd(&g_total, c);
        g_ptr[i] = p;
        g_pos[i] = p;
    }
    if (blockIdx.x == 0) {
        g_stats0[threadIdx.x] = 0.0f;
        g_stats0[256 + threadIdx.x] = 0.0f;
    }
    if (blockIdx.x == 1) {
        g_stats1[threadIdx.x] = 0.0f;
        g_stats1[256 + threadIdx.x] = 0.0f;
    }
}

// fp16 weight transpose + head bias + x -> fp16 (NO graph dependence)
__global__ void k_wcvt(const float* __restrict__ x,
                       const float* __restrict__ W0, const float* __restrict__ W1,
                       const float* __restrict__ Wmu, const float* __restrict__ Wlv,
                       const float* __restrict__ bmu, const float* __restrict__ blv) {
    int b = blockIdx.x;
    if (b < 768) {
        int idx = b * 256 + threadIdx.x;      // 0 .. 196607
        if (idx < 65536) {
            int n = idx >> 8, k = idx & 255;
            g_w0t[idx] = __float2half(W0[k * 256 + n]);
        } else if (idx < 131072) {
            int j = idx - 65536; int n = j >> 8, k = j & 255;
            g_w1t[j] = __float2half(W1[k * 256 + n]);
        } else {
            int j = idx - 131072; int n = j >> 8, k = j & 255;
            float v = (n < 128) ? Wmu[k * 128 + n] : Wlv[k * 128 + (n - 128)];
            g_wct[j] = __float2half(v);
        }
        return;
    }
    if (b == 768) {
        int t = threadIdx.x;
        g_bcat[t] = (t < 128) ? bmu[t] : blv[t - 128];
        return;
    }
    // x conversion: 6250 blocks
    size_t j = (size_t)(b - 769) * 2048 + (size_t)threadIdx.x * 8;
    float4 v0 = *(const float4*)&x[j];
    float4 v1 = *(const float4*)&x[j + 4];
    __half2 h0 = __floats2half2_rn(v0.x, v0.y);
    __half2 h1 = __floats2half2_rn(v0.z, v0.w);
    __half2 h2 = __floats2half2_rn(v1.x, v1.y);
    __half2 h3 = __floats2half2_rn(v1.z, v1.w);
    uint4 o = make_uint4(*(uint32_t*)&h0, *(uint32_t*)&h1,
                         *(uint32_t*)&h2, *(uint32_t*)&h3);
    *(uint4*)&g_a16[j] = o;
}

__global__ void k_fill(const int* __restrict__ src, const int* __restrict__ dst) {
    int e = blockIdx.x * blockDim.x + threadIdx.x;
    if (e >= EE) return;
    int s = src[e], d = dst[e];
    int p = atomicAdd(&g_pos[d], 1);
    float c = g_dinv[s] * g_dinv[d];
    g_csr[p] = make_int2(s, __float_as_int(c));
}

// ---------------- cp.async pipelined fp16 GEMM (4-stage, BN-table in smem) ----
// FUSE_BN: each block computes the 256 BN scale/shift pairs from `stats`
// (+gamma/beta) into smem during the cp.async prologue shadow, then applies
// them on A-fragments. No separate bn_final kernel needed.
#define STG_H (128 * KP2)               // halves per (A or B) stage
#define NSTG  4
#define SMEM_BYTES (NSTG * 2 * STG_H * 2 + 2048)   // stages + 512-float BN table
template <bool FUSE_BN, bool OUT16>
__global__ void __launch_bounds__(256, 2)
gemm_ca(const __half* __restrict__ Ah, const __half* __restrict__ Wt,
        const float* __restrict__ bias, float* __restrict__ Cf,
        __half* __restrict__ Ch, int M,
        const float* __restrict__ stats,
        const float* __restrict__ gamma, const float* __restrict__ beta) {
    extern __shared__ __half sm[];
    float* ssb = (float*)(sm + NSTG * 2 * STG_H);   // [0:256) scale, [256:512) shift

    int tid  = threadIdx.x;
    int wid  = tid >> 5, lane = tid & 31;
    int g    = lane >> 2, tg = lane & 3;
    int mb   = (wid & 3) * 32;
    int nb   = (wid >> 2) * 64;
    int rowBase = blockIdx.x * 128;
    int colBase = blockIdx.y * 128;

    uint32_t smBase = (uint32_t)__cvta_generic_to_shared(sm);

    int r_a = tid >> 2, c8_a = (tid & 3) << 3;
    int gr   = rowBase + r_a;       int gr2  = (gr   < M) ? gr   : M - 1;
    int gr_b = rowBase + r_a + 64;  int gr2b = (gr_b < M) ? gr_b : M - 1;

    auto load_stage = [&](int st, int t) {
        int k0 = t * 32;
        uint32_t aBase = smBase + (uint32_t)(st * 2 * STG_H) * 2u;
        uint32_t bBase = aBase + (uint32_t)STG_H * 2u;
        cp16(aBase + (uint32_t)(r_a * KP2 + c8_a) * 2u,
             &Ah[(size_t)gr2 * 256 + k0 + c8_a]);
        cp16(aBase + (uint32_t)((r_a + 64) * KP2 + c8_a) * 2u,
             &Ah[(size_t)gr2b * 256 + k0 + c8_a]);
        cp16_ca(bBase + (uint32_t)(r_a * KP2 + c8_a) * 2u,
                &Wt[(size_t)(colBase + r_a) * 256 + k0 + c8_a]);
        cp16_ca(bBase + (uint32_t)((r_a + 64) * KP2 + c8_a) * 2u,
                &Wt[(size_t)(colBase + r_a + 64) * 256 + k0 + c8_a]);
        asm volatile("cp.async.commit_group;\n" ::: "memory");
    };

    float acc[2][8][4] = {};

    int lm  = lane >> 3;           // ldmatrix matrix index 0..3
    int lr  = lane & 7;            // row within matrix

    load_stage(0, 0);
    load_stage(1, 1);
    load_stage(2, 2);

    // build BN table in the cp.async shadow (visible after loop's syncthreads)
    if (FUSE_BN) {
        float inv_n = 1.0f / (float)NN;
        float m  = stats[tid] * inv_n;
        float vv = stats[HDIM + tid] * inv_n - m * m;
        float sc = gamma[tid] * rsqrtf(vv + BN_EPS);
        ssb[tid]        = sc;
        ssb[256 + tid]  = beta[tid] - m * sc;
    }

#pragma unroll
    for (int t = 0; t < 8; t++) {
        if (t <= 5)      asm volatile("cp.async.wait_group 2;\n" ::: "memory");
        else if (t == 6) asm volatile("cp.async.wait_group 1;\n" ::: "memory");
        else             asm volatile("cp.async.wait_group 0;\n" ::: "memory");
        __syncthreads();
        if (t + 3 < 8) load_stage((t + 3) % NSTG, t + 3);

        int st = t % NSTG;
        uint32_t aBase = smBase + (uint32_t)(st * 2 * STG_H) * 2u;
        uint32_t bBase = aBase + (uint32_t)STG_H * 2u;
        int k0 = t * 32;

#pragma unroll
        for (int ks = 0; ks < 2; ks++) {
            int kk = ks * 16;
            uint32_t a[2][4];
#pragma unroll
            for (int im = 0; im < 2; im++) {
                int row = mb + im * 16 + (lane & 15);
                int col = kk + ((lane >> 4) << 3);
                uint32_t addr = aBase + (uint32_t)(row * KP2 + col) * 2u;
                asm volatile(
                    "ldmatrix.sync.aligned.m8n8.x4.shared.b16 {%0,%1,%2,%3}, [%4];"
                    : "=r"(a[im][0]), "=r"(a[im][1]), "=r"(a[im][2]), "=r"(a[im][3])
                    : "r"(addr));
            }
            if (FUSE_BN) {
                int kb = k0 + kk + tg * 2;
                float2 sA = *(const float2*)&ssb[kb];
                float2 hA = *(const float2*)&ssb[256 + kb];
                float2 sB = *(const float2*)&ssb[kb + 8];
                float2 hB = *(const float2*)&ssb[256 + kb + 8];
#pragma unroll
                for (int im = 0; im < 2; im++) {
                    a[im][0] = bnfrag(a[im][0], sA, hA);
                    a[im][1] = bnfrag(a[im][1], sA, hA);
                    a[im][2] = bnfrag(a[im][2], sB, hB);
                    a[im][3] = bnfrag(a[im][3], sB, hB);
                }
            }
            uint32_t bf[8][2];
#pragma unroll
            for (int ntp = 0; ntp < 4; ntp++) {
                int row_n = nb + ntp * 16 + ((lm >> 1) << 3) + lr;
                int col   = kk + ((lm & 1) << 3);
                uint32_t addr = bBase + (uint32_t)(row_n * KP2 + col) * 2u;
                asm volatile(
                    "ldmatrix.sync.aligned.m8n8.x4.shared.b16 {%0,%1,%2,%3}, [%4];"
                    : "=r"(bf[ntp * 2][0]),     "=r"(bf[ntp * 2][1]),
                      "=r"(bf[ntp * 2 + 1][0]), "=r"(bf[ntp * 2 + 1][1])
                    : "r"(addr));
            }
#pragma unroll
            for (int nt = 0; nt < 8; nt++) {
                mma_f16(acc[0][nt], a[0], bf[nt][0], bf[nt][1]);
                mma_f16(acc[1][nt], a[1], bf[nt][0], bf[nt][1]);
            }
        }
    }

    // ---- epilogue ----
#pragma unroll
    for (int im = 0; im < 2; im++) {
#pragma unroll
        for (int nt = 0; nt < 8; nt++) {
            int row0 = rowBase + mb + im * 16 + g;
            int col  = colBase + nb + nt * 8 + tg * 2;
            float bx = 0.f, by = 0.f;
            if (bias) { bx = bias[col]; by = bias[col + 1]; }
#pragma unroll
            for (int h = 0; h < 2; h++) {
                int row = row0 + h * 8;
                if (row < M) {
                    float ox = acc[im][nt][h * 2 + 0] + bx;
                    float oy = acc[im][nt][h * 2 + 1] + by;
                    if (OUT16) {
                        *(__half2*)&Ch[(size_t)row * 256 + col] =
                            __floats2half2_rn(ox, oy);
                    } else {
                        if (col < 128)
                            *(float2*)&Cf[(size_t)row * 128 + col] =
                                make_float2(ox, oy);
                        else
                            *(float2*)&Cf[(size_t)NN * 128 + (size_t)row * 128 + (col - 128)] =
                                make_float2(ox, oy);
                    }
                }
            }
        }
    }
}

// ---------------- CSR aggregation, MLP=4 (proven), + fused BN stats ----------
__device__ __forceinline__ void fma8(float* acc, uint4 r, float c) {
    __half2* hp = (__half2*)&r;
#pragma unroll
    for (int q = 0; q < 4; q++) {
        float2 p = __half22float2(hp[q]);
        acc[q * 2]     += c * p.x;
        acc[q * 2 + 1] += c * p.y;
    }
}

__global__ void k_agg_csr(const __half* __restrict__ h, __half* __restrict__ out,
                          const float* __restrict__ bias, float* __restrict__ stats) {
    __shared__ float s_sum[8][256];
    __shared__ float s_sq [8][256];

    int grp  = threadIdx.x >> 5;     // 0..7
    int lane = threadIdx.x & 31;
    int node = blockIdx.x * 8 + grp;
    int f = lane * 8;

    float acc[8] = {};
    if (node < NN) {
        float di = g_dinv[node];
        float cs = di * di;
#pragma unroll
        for (int q = 0; q < 8; q++) acc[q] = bias[f + q];
        fma8(acc, *(const uint4*)&h[(size_t)node * 256 + f], cs);

        int beg = g_ptr[node];
        int end = beg + g_cnt[node];
        int2 rec = make_int2(0, 0);
        if (lane < 4 && beg + lane < end) rec = g_csr[beg + lane];

        for (int j = beg; j < end; j += 4) {
            int2 cur = rec;
            int jn = j + 4;
            int2 nx = make_int2(0, 0);
            if (lane < 4 && jn + lane < end) nx = g_csr[jn + lane];
            rec = nx;
            int take = end - j;      // warp-uniform

            int   s0 = __shfl_sync(0xffffffffu, cur.x, 0);
            float c0 = __int_as_float(__shfl_sync(0xffffffffu, cur.y, 0));
            int   s1 = __shfl_sync(0xffffffffu, cur.x, 1);
            float c1 = __int_as_float(__shfl_sync(0xffffffffu, cur.y, 1));
            int   s2 = __shfl_sync(0xffffffffu, cur.x, 2);
            float c2 = __int_as_float(__shfl_sync(0xffffffffu, cur.y, 2));
            int   s3 = __shfl_sync(0xffffffffu, cur.x, 3);
            float c3 = __int_as_float(__shfl_sync(0xffffffffu, cur.y, 3));

            uint4 r0 = *(const uint4*)&h[(size_t)s0 * 256 + f];
            if (take > 1) {
                uint4 r1 = *(const uint4*)&h[(size_t)s1 * 256 + f];
                if (take > 2) {
                    uint4 r2 = *(const uint4*)&h[(size_t)s2 * 256 + f];
                    if (take > 3) {
                        uint4 r3 = *(const uint4*)&h[(size_t)s3 * 256 + f];
                        fma8(acc, r3, c3);
                    }
                    fma8(acc, r2, c2);
                }
                fma8(acc, r1, c1);
            }
            fma8(acc, r0, c0);
        }

        __half2 o0 = __floats2half2_rn(acc[0], acc[1]);
        __half2 o1 = __floats2half2_rn(acc[2], acc[3]);
        __half2 o2 = __floats2half2_rn(acc[4], acc[5]);
        __half2 o3 = __floats2half2_rn(acc[6], acc[7]);
        uint4 ov = make_uint4(*(uint32_t*)&o0, *(uint32_t*)&o1,
                              *(uint32_t*)&o2, *(uint32_t*)&o3);
        *(uint4*)&out[(size_t)node * 256 + f] = ov;
    }

#pragma unroll
    for (int q = 0; q < 8; q++) {
        s_sum[grp][f + q] = acc[q];
        s_sq [grp][f + q] = acc[q] * acc[q];
    }
    __syncthreads();

    int t = threadIdx.x;   // feature
    float s = 0.f, q = 0.f;
#pragma unroll
    for (int gi = 0; gi < 8; gi++) { s += s_sum[gi][t]; q += s_sq[gi][t]; }
    atomicAdd(&stats[t], s);
    atomicAdd(&stats[HDIM + t], q);
}

// ---------------- launch ----------------
extern "C" void kernel_launch(void* const* d_in, const int* in_sizes, int n_in,
                              void* d_out, int out_size) {
    const float* x   = (const float*)d_in[0];
    const int*   ei  = (const int*)  d_in[1];   // [2, E]: src then dst
    const float* W0  = (const float*)d_in[2];
    const float* b0  = (const float*)d_in[3];
    const float* g0  = (const float*)d_in[4];
    const float* be0 = (const float*)d_in[5];
    const float* W1  = (const float*)d_in[6];
    const float* b1  = (const float*)d_in[7];
    const float* g1  = (const float*)d_in[8];
    const float* be1 = (const float*)d_in[9];
    const float* Wmu = (const float*)d_in[10];
    const float* bmu = (const float*)d_in[11];
    const float* Wlv = (const float*)d_in[12];
    const float* blv = (const float*)d_in[13];
    float* out = (float*)d_out;

    const int* src = ei;
    const int* dst = ei + EE;

    __half *h16 = nullptr, *a16 = nullptr, *w0t = nullptr, *w1t = nullptr, *wct = nullptr;
    float  *bcat = nullptr, *st0 = nullptr, *st1 = nullptr;
    cudaGetSymbolAddress((void**)&h16,  g_h16);
    cudaGetSymbolAddress((void**)&a16,  g_a16);
    cudaGetSymbolAddress((void**)&w0t,  g_w0t);
    cudaGetSymbolAddress((void**)&w1t,  g_w1t);
    cudaGetSymbolAddress((void**)&wct,  g_wct);
    cudaGetSymbolAddress((void**)&bcat, g_bcat);
    cudaGetSymbolAddress((void**)&st0,  g_stats0);
    cudaGetSymbolAddress((void**)&st1,  g_stats1);

    // side streams + events (created once, outside any capture)
    static cudaStream_t s1 = nullptr, s2 = nullptr;
    static cudaEvent_t  evF = nullptr, evGemm = nullptr, evDinv = nullptr, evCsr = nullptr;
    if (!s1) {
        cudaStreamCreateWithFlags(&s1, cudaStreamNonBlocking);
        cudaStreamCreateWithFlags(&s2, cudaStreamNonBlocking);
        cudaEventCreateWithFlags(&evF,    cudaEventDisableTiming);
        cudaEventCreateWithFlags(&evGemm, cudaEventDisableTiming);
        cudaEventCreateWithFlags(&evDinv, cudaEventDisableTiming);
        cudaEventCreateWithFlags(&evCsr,  cudaEventDisableTiming);
    }

    const int NB_N  = SCAN_B;
    const int NB_E  = (EE + 255) / 256;
    const int NB_AG = (NN + 7) / 8;             // 6250
    const int NB_W  = 769 + 6250;               // weights + bias + x-convert
    const dim3 G_GEMM((NN + 127) / 128, 2);     // 391 x 2

    cudaFuncSetAttribute(gemm_ca<false, true>,
                         cudaFuncAttributeMaxDynamicSharedMemorySize, SMEM_BYTES);
    cudaFuncSetAttribute(gemm_ca<true, true>,
                         cudaFuncAttributeMaxDynamicSharedMemorySize, SMEM_BYTES);
    cudaFuncSetAttribute(gemm_ca<true, false>,
                         cudaFuncAttributeMaxDynamicSharedMemorySize, SMEM_BYTES);

    // fork point
    cudaEventRecord(evF, 0);

    // chain A (s1): weight/x conversion -> layer-0 GEMM (independent of graph)
    cudaStreamWaitEvent(s1, evF, 0);
    k_wcvt<<<NB_W, 256, 0, s1>>>(x, W0, W1, Wmu, Wlv, bmu, blv);
    gemm_ca<false, true><<<G_GEMM, 256, SMEM_BYTES, s1>>>(
        a16, w0t, nullptr, nullptr, h16, NN, nullptr, nullptr, nullptr);
    cudaEventRecord(evGemm, s1);

    // chain B (default): degree counts -> dinv+ptr+stats-zero (fused)
    k_cnt_zero<<<NB_N, 256>>>();
    k_cnt     <<<NB_E, 256>>>(dst);
    k_dinv    <<<NB_N, 256>>>();
    cudaEventRecord(evDinv, 0);

    // chain C (s2): CSR fill (needs dinv+ptr)
    cudaStreamWaitEvent(s2, evDinv, 0);
    k_fill<<<NB_E, 256, 0, s2>>>(src, dst);
    cudaEventRecord(evCsr, s2);

    // join everything on default stream
    cudaStreamWaitEvent(0, evGemm, 0);
    cudaStreamWaitEvent(0, evCsr, 0);

    // layer 0 aggregation (stats -> st0); BN applied inside gemm1
    k_agg_csr<<<NB_AG, 256>>>(h16, a16, b0, st0);

    // layer 1
    gemm_ca<true, true><<<G_GEMM, 256, SMEM_BYTES>>>(
        a16, w1t, nullptr, nullptr, h16, NN, st0, g0, be0);
    k_agg_csr<<<NB_AG, 256>>>(h16, a16, b1, st1);

    // heads: combined mu|logvar GEMM with split epilogue, BN from st1
    gemm_ca<true, false><<<G_GEMM, 256, SMEM_BYTES>>>(
        a16, wct, bcat, out, nullptr, NN, st1, g1, be1);
}